// round 10
// baseline (speedup 1.0000x reference)
#include <cuda_runtime.h>
#include <math.h>

#define EDIM   128
#define LSEQ   512
#define NB     16
#define NFEAT  32
#define NBINS  8193
#define LAMBDA 0.01f
#define SLICE  28
#define NBLK   293     // ceil(8193/28)

typedef unsigned long long u64;

// Persistent scratch. Index p is the PERMUTED bin order (DIF slot order).
__device__ __align__(256) float2 d_X[NB][8200];
__device__ __align__(256) float  d_TA[8200][8];
__device__ __align__(256) float  d_TB[8200][8];
__device__ __align__(256) float  d_part[NBLK][16384];   // per-slice partial H1

// ---- packed f32x2 helpers ----
__device__ __forceinline__ u64 fma2(u64 a, u64 b, u64 c) {
    u64 d; asm("fma.rn.f32x2 %0, %1, %2, %3;" : "=l"(d) : "l"(a), "l"(b), "l"(c));
    return d;
}
__device__ __forceinline__ u64 add2(u64 a, u64 b) {
    u64 d; asm("add.rn.f32x2 %0, %1, %2;" : "=l"(d) : "l"(a), "l"(b));
    return d;
}
__device__ __forceinline__ u64 pack2(float v) {
    u64 d; asm("mov.b64 %0, {%1, %1};" : "=l"(d) : "f"(v)); return d;
}
__device__ __forceinline__ u64 packpair(float a, float b) {
    u64 d; asm("mov.b64 %0, {%1, %2};" : "=l"(d) : "f"(a), "f"(b)); return d;
}
__device__ __forceinline__ float2 unpack2(u64 p) {
    float2 r; asm("mov.b64 {%0, %1}, %2;" : "=f"(r.x), "=f"(r.y) : "l"(p));
    return r;
}
__device__ __forceinline__ u64 relu2(u64 v) {
    float2 u = unpack2(v);
    return packpair(fmaxf(u.x, 0.0f), fmaxf(u.y, 0.0f));
}

__device__ __forceinline__ float2 cmul(float2 a, float2 b) {
    return make_float2(a.x * b.x - a.y * b.y, a.x * b.y + a.y * b.x);
}
__device__ __forceinline__ float2 cadd(float2 a, float2 b) {
    return make_float2(a.x + b.x, a.y + b.y);
}
__device__ __forceinline__ float2 csub(float2 a, float2 b) {
    return make_float2(a.x - b.x, a.y - b.y);
}

#define PAD(i) ((i) + ((i) >> 4))

// ---------------------------------------------------------------------------
// Kernel 1: PREP (reverted to R8 radix-4 DIF). 384 blocks x 256 threads.
// ---------------------------------------------------------------------------
__global__ void __launch_bounds__(256)
prep(const float* __restrict__ x, const float* __restrict__ emb10) {
    __shared__ float2 buf[2][546];
    __shared__ float2 tw[256];
    __shared__ float2 w32[2][32];
    const int tid = threadIdx.x;
    const int sub = tid >> 7;
    const int t   = tid & 127;
    const int fftid = blockIdx.x * 2 + sub;
    const bool fwd = (fftid < 512);
    const int idx = fwd ? fftid : fftid - 512;
    const int r = idx & 31;
    float2* B = buf[sub];

    {
        float s, c;
        sincospif((float)tid * (1.0f / 256.0f), &s, &c);
        tw[tid] = make_float2(c, -s);
    }
    if (t < 32) {
        int ph = (r * t) & 31;
        float s, c;
        sincospif((float)ph * (1.0f / 16.0f), &s, &c);
        w32[sub][t] = make_float2(c, -s);
    }
    __syncthreads();

    if (fwd) {
        const int b = idx >> 5;
        #pragma unroll
        for (int li = 0; li < 4; li++) {
            const int l = t + 128 * li;
            const float4* xr4 = (const float4*)(x + (b * LSEQ + l) * NFEAT);
            float sr = 0.0f, si = 0.0f;
            #pragma unroll
            for (int i = 0; i < 8; i++) {
                float4 v4 = xr4[i];
                float2 wa = w32[sub][4 * i + 0], wb = w32[sub][4 * i + 1];
                float2 wc = w32[sub][4 * i + 2], wd = w32[sub][4 * i + 3];
                sr = fmaf(v4.x, wa.x, sr); si = fmaf(v4.x, wa.y, si);
                sr = fmaf(v4.y, wb.x, sr); si = fmaf(v4.y, wb.y, si);
                sr = fmaf(v4.z, wc.x, sr); si = fmaf(v4.z, wc.y, si);
                sr = fmaf(v4.w, wd.x, sr); si = fmaf(v4.w, wd.y, si);
            }
            float ss, cc;
            sincospif((float)(r * l) * (1.0f / 8192.0f), &ss, &cc);
            B[PAD(l)] = make_float2(fmaf(sr, cc, si * ss), fmaf(si, cc, -sr * ss));
        }
    } else {
        const int j = idx >> 5;
        #pragma unroll
        for (int li = 0; li < 4; li++) {
            const int l = t + 128 * li;
            float ev = emb10[l * 8 + j];
            float ss, cc;
            sincospif((float)(r * l) * (1.0f / 8192.0f), &ss, &cc);
            B[PAD(l)] = make_float2(ev * cc, -ev * ss);
        }
    }
    __syncthreads();

    #pragma unroll
    for (int s = 8; s >= 2; s -= 2) {
        const int h = 1 << s, h2 = h >> 1;
        const int j = t & (h2 - 1);
        const int base = ((t >> (s - 1)) << (s + 1)) + j;
        float2 a  = B[PAD(base)];
        float2 bb = B[PAD(base + h2)];
        float2 c  = B[PAD(base + h)];
        float2 d  = B[PAD(base + h + h2)];
        float2 wA = tw[j << (8 - s)];
        float2 wB = tw[(j + h2) << (8 - s)];
        float2 a1 = cadd(a, c),  c1 = cmul(csub(a, c),  wA);
        float2 b1 = cadd(bb, d), d1 = cmul(csub(bb, d), wB);
        float2 w2 = tw[j << (9 - s)];
        B[PAD(base)]          = cadd(a1, b1);
        B[PAD(base + h2)]     = cmul(csub(a1, b1), w2);
        B[PAD(base + h)]      = cadd(c1, d1);
        B[PAD(base + h + h2)] = cmul(csub(c1, d1), w2);
        __syncthreads();
    }
    #pragma unroll
    for (int k = 0; k < 2; k++) {
        int i = t + 128 * k;
        float2 u = B[PAD(2 * i)];
        float2 v = B[PAD(2 * i + 1)];
        B[PAD(2 * i)]     = cadd(u, v);
        B[PAD(2 * i + 1)] = csub(u, v);
    }
    __syncthreads();

    if (fwd) {
        const int b = idx >> 5;
        const float sc = 1.0f / 128.0f;
        #pragma unroll
        for (int k = 0; k < 2; k++) {
            int m = t + 128 * k;
            float2 v = B[PAD(2 * m)];
            d_X[b][r * 256 + m] = make_float2(v.x * sc, v.y * sc);
        }
        if (r == 0 && t == 0) {
            float2 v = B[PAD(1)];
            d_X[b][8192] = make_float2(v.x * sc, v.y * sc);
        }
    } else {
        const int j = idx >> 5;
        #pragma unroll
        for (int k = 0; k < 2; k++) {
            int m = t + 128 * k;
            int p = r * 256 + m;
            float sf = (p == 0) ? (1.0f / 128.0f) : (2.0f / 128.0f);
            float2 v = B[PAD(2 * m)];
            d_TA[p][j] = sf * v.x;
            d_TB[p][j] = sf * v.y;
        }
        if (r == 0 && t == 0) {
            float2 v = B[PAD(1)];
            d_TA[8192][j] = (1.0f / 128.0f) * v.x;
            d_TB[8192][j] = (1.0f / 128.0f) * v.y;
        }
    }
}

// ---------------------------------------------------------------------------
// Kernel 2: gc_gemm, f-sliced. Block = one 28-bin f-slice, covering ALL
// (e,b): thread (u = tid&31, v = tid>>5) owns e in [4u,4u+4), b in {2v,2v+1}.
// Table read once per slice (broadcast within warps). Writes partial H1.
// ---------------------------------------------------------------------------
__global__ void __launch_bounds__(256)
gc_gemm(const float* __restrict__ emb,
        const float* __restrict__ w0, const float* __restrict__ b0,
        const float* __restrict__ w1, const float* __restrict__ b1,
        const float* __restrict__ w2, const float* __restrict__ b2) {
    __shared__ float cst[13][EDIM];
    const int bi  = blockIdx.x;
    const int pA  = bi * SLICE;
    const int pB  = min(pA + SLICE, NBINS);
    const int tid = threadIdx.x;
    const int u   = tid & 31;      // e0 = 4u
    const int v   = tid >> 5;      // b = 2v, 2v+1

    // cooperative constant staging
    if (tid < EDIM) {
        int e = tid;
        cst[0][e]  = w0[e * 129];          cst[1][e]  = w0[16384 + e * 129];
        cst[2][e]  = b0[e];                cst[3][e]  = b0[128 + e];
        cst[4][e]  = w1[e * 129];          cst[5][e]  = w1[16384 + e * 129];
        cst[6][e]  = b1[e];                cst[7][e]  = b1[128 + e];
        cst[8][e]  = w2[e * 129];          cst[9][e]  = w2[16384 + e * 129];
        cst[10][e] = b2[e];                cst[11][e] = b2[128 + e];
        cst[12][e] = emb[e];
    }
    __syncthreads();

    const int e0 = 4 * u;
    u64 pD00[2], pD01[2], pD01n[2], pC00[2], pC01[2];
    u64 pd10[2], pd11[2], pd11n[2], pC10[2], pC11[2];
    u64 pd20[2], pd21[2], pd21n[2], pC20[2], pC21[2];
    #pragma unroll
    for (int pp = 0; pp < 2; pp++) {
        int eA = e0 + 2 * pp, eB = eA + 1;
        float emA = cst[12][eA], emB = cst[12][eB];
        float a01 = emA * cst[1][eA], q01 = emB * cst[1][eB];
        pD00[pp]  = packpair(emA * cst[0][eA], emB * cst[0][eB]);
        pD01[pp]  = packpair(a01, q01);
        pD01n[pp] = packpair(-a01, -q01);
        pC00[pp]  = packpair(cst[2][eA], cst[2][eB]);
        pC01[pp]  = packpair(cst[3][eA], cst[3][eB]);
        float a11 = cst[5][eA], q11 = cst[5][eB];
        pd10[pp]  = packpair(cst[4][eA], cst[4][eB]);
        pd11[pp]  = packpair(a11, q11);
        pd11n[pp] = packpair(-a11, -q11);
        pC10[pp]  = packpair(cst[6][eA], cst[6][eB]);
        pC11[pp]  = packpair(cst[7][eA], cst[7][eB]);
        float a21 = cst[9][eA], q21 = cst[9][eB];
        pd20[pp]  = packpair(cst[8][eA], cst[8][eB]);
        pd21[pp]  = packpair(a21, q21);
        pd21n[pp] = packpair(-a21, -q21);
        pC20[pp]  = packpair(cst[10][eA], cst[10][eB]);
        pC21[pp]  = packpair(cst[11][eA], cst[11][eB]);
    }
    const u64 NL = pack2(-LAMBDA);

    u64 acc[2][4][4];
    #pragma unroll
    for (int bb = 0; bb < 2; bb++)
        #pragma unroll
        for (int eo = 0; eo < 4; eo++)
            #pragma unroll
            for (int jp = 0; jp < 4; jp++) acc[bb][eo][jp] = 0ull;

    #pragma unroll 2
    for (int p = pA; p < pB; p++) {
        float2 X0 = d_X[2 * v][p];
        float2 X1 = d_X[2 * v + 1][p];
        ulonglong2 taL = *(const ulonglong2*)&d_TA[p][0];
        ulonglong2 taH = *(const ulonglong2*)&d_TA[p][4];
        ulonglong2 tbL = *(const ulonglong2*)&d_TB[p][0];
        ulonglong2 tbH = *(const ulonglong2*)&d_TB[p][4];
        #pragma unroll
        for (int bb = 0; bb < 2; bb++) {
            u64 xr2 = pack2(bb ? X1.x : X0.x);
            u64 xi2 = pack2(bb ? X1.y : X0.y);
            #pragma unroll
            for (int pp = 0; pp < 2; pp++) {
                u64 r1r = fma2(xr2, pD00[pp], fma2(xi2, pD01n[pp], pC00[pp]));
                u64 o1r = relu2(r1r);
                u64 r1i = fma2(xi2, pD00[pp], fma2(xr2, pD01[pp], pC01[pp]));
                u64 o1i = relu2(r1i);
                u64 pr = relu2(add2(r1r, NL));
                u64 pi = relu2(add2(r1i, NL));
                u64 r2r = fma2(o1r, pd10[pp], fma2(o1i, pd11n[pp], pC10[pp]));
                u64 o2r = relu2(r2r);
                u64 r2i = fma2(o1i, pd10[pp], fma2(o2r, pd11[pp], pC11[pp]));
                u64 o2i = relu2(r2i);
                pr = add2(pr, relu2(add2(r2r, NL)));
                pi = add2(pi, relu2(add2(r2i, NL)));
                u64 r3r = fma2(o2r, pd20[pp], fma2(o2i, pd21n[pp], pC20[pp]));
                u64 o3r = relu2(r3r);
                u64 r3i = fma2(o2i, pd20[pp], fma2(o3r, pd21[pp], pC21[pp]));
                u64 zr2 = add2(pr, relu2(add2(r3r, NL)));
                u64 zi2 = add2(pi, relu2(add2(r3i, NL)));
                float2 zrv = unpack2(zr2), ziv = unpack2(zi2);
                {
                    u64 zr = pack2(zrv.x), zi = pack2(ziv.x);
                    u64* A = acc[bb][2 * pp];
                    A[0] = fma2(zr, taL.x, fma2(zi, tbL.x, A[0]));
                    A[1] = fma2(zr, taL.y, fma2(zi, tbL.y, A[1]));
                    A[2] = fma2(zr, taH.x, fma2(zi, tbH.x, A[2]));
                    A[3] = fma2(zr, taH.y, fma2(zi, tbH.y, A[3]));
                }
                {
                    u64 zr = pack2(zrv.y), zi = pack2(ziv.y);
                    u64* A = acc[bb][2 * pp + 1];
                    A[0] = fma2(zr, taL.x, fma2(zi, tbL.x, A[0]));
                    A[1] = fma2(zr, taL.y, fma2(zi, tbL.y, A[1]));
                    A[2] = fma2(zr, taH.x, fma2(zi, tbH.x, A[2]));
                    A[3] = fma2(zr, taH.y, fma2(zi, tbH.y, A[3]));
                }
            }
        }
    }

    // write partial H1: thread owns disjoint (b,e,j) cells
    #pragma unroll
    for (int bb = 0; bb < 2; bb++) {
        float* dst = &d_part[bi][(2 * v + bb) * 1024 + e0 * 8];
        #pragma unroll
        for (int eo = 0; eo < 4; eo++)
            #pragma unroll
            for (int jp = 0; jp < 4; jp++)
                *(u64*)&dst[eo * 8 + 2 * jp] = acc[bb][eo][jp];
    }
}

// ---------------------------------------------------------------------------
// Kernel 3: partial reduction + bias projection + final MLP. 16 x 512.
// ---------------------------------------------------------------------------
__global__ void __launch_bounds__(512)
mlp_kernel(const float* __restrict__ x, const float* __restrict__ emb,
           const float* __restrict__ emb10,
           const float* __restrict__ fc1w, const float* __restrict__ fc1b,
           const float* __restrict__ fc2w, const float* __restrict__ fc2b,
           const float* __restrict__ fc3w, const float* __restrict__ fc3b,
           float* __restrict__ out) {
    __shared__ __align__(16) float h[1024];
    __shared__ __align__(16) float v1[64];
    __shared__ __align__(16) float v2[256];
    __shared__ float xs[LSEQ];
    __shared__ float Ps[8];
    const int b = blockIdx.x;
    const int tid = threadIdx.x;
    const int w = tid >> 5, lane = tid & 31;

    xs[tid] = x[(b * LSEQ + tid) * NFEAT];
    __syncthreads();
    if (w < 8) {
        float s = 0.0f;
        #pragma unroll
        for (int i = 0; i < 16; i++)
            s += xs[lane + 32 * i] * emb10[(lane + 32 * i) * 8 + w];
        #pragma unroll
        for (int o = 16; o; o >>= 1) s += __shfl_down_sync(0xFFFFFFFFu, s, o);
        if (lane == 0) Ps[w] = s;
    }
    __syncthreads();

    // h = sum_k part[k] + emb[e]*P[j]
    #pragma unroll
    for (int k2 = 0; k2 < 2; k2++) {
        int i = tid + 512 * k2;
        const float* pp = &d_part[0][b * 1024 + i];
        float s0 = 0.0f, s1 = 0.0f, s2 = 0.0f, s3 = 0.0f;
        int k = 0;
        for (; k + 4 <= NBLK; k += 4) {
            s0 += pp[(size_t)(k + 0) * 16384];
            s1 += pp[(size_t)(k + 1) * 16384];
            s2 += pp[(size_t)(k + 2) * 16384];
            s3 += pp[(size_t)(k + 3) * 16384];
        }
        for (; k < NBLK; k++) s0 += pp[(size_t)k * 16384];
        h[i] = (s0 + s1) + (s2 + s3) + emb[i >> 3] * Ps[i & 7];
    }
    __syncthreads();

    {
        const int j = tid >> 3, sub = tid & 7;
        const float4* fw = (const float4*)(fc1w + j * 1024);
        const float4* h4 = (const float4*)h;
        float s = 0.0f;
        #pragma unroll
        for (int i = 0; i < 32; i++) {
            float4 a = fw[sub + 8 * i];
            float4 v = h4[sub + 8 * i];
            s += a.x * v.x + a.y * v.y + a.z * v.z + a.w * v.w;
        }
        s += __shfl_down_sync(0xFFFFFFFFu, s, 4, 8);
        s += __shfl_down_sync(0xFFFFFFFFu, s, 2, 8);
        s += __shfl_down_sync(0xFFFFFFFFu, s, 1, 8);
        if (sub == 0) {
            s += fc1b[j];
            v1[j] = s > 0.0f ? s : 0.01f * s;
        }
    }
    __syncthreads();

    {
        const int j = tid >> 1, sub = tid & 1;
        const float4* fw = (const float4*)(fc2w + j * 64);
        const float4* v14 = (const float4*)v1;
        float s = 0.0f;
        #pragma unroll
        for (int i = 0; i < 8; i++) {
            float4 a = fw[sub * 8 + i];
            float4 v = v14[sub * 8 + i];
            s += a.x * v.x + a.y * v.y + a.z * v.z + a.w * v.w;
        }
        s += __shfl_down_sync(0xFFFFFFFFu, s, 1, 2);
        if (sub == 0) {
            s += fc2b[j];
            v2[j] = s > 0.0f ? s : 0.01f * s;
        }
    }
    __syncthreads();

    if (tid < 384) {
        const int j = tid >> 2, sub = tid & 3;
        const float4* fw = (const float4*)(fc3w + j * 256);
        const float4* v24 = (const float4*)v2;
        float s = 0.0f;
        #pragma unroll
        for (int i = 0; i < 16; i++) {
            float4 a = fw[sub * 16 + i];
            float4 v = v24[sub * 16 + i];
            s += a.x * v.x + a.y * v.y + a.z * v.z + a.w * v.w;
        }
        s += __shfl_down_sync(0xFFFFFFFFu, s, 2, 4);
        s += __shfl_down_sync(0xFFFFFFFFu, s, 1, 4);
        if (sub == 0) out[b * 96 + j] = s + fc3b[j];
    }
}

// ---------------------------------------------------------------------------
extern "C" void kernel_launch(void* const* d_in, const int* in_sizes, int n_in,
                              void* d_out, int out_size) {
    const float* x     = (const float*)d_in[0];
    const float* emb   = (const float*)d_in[1];
    const float* w0    = (const float*)d_in[2];
    const float* b0    = (const float*)d_in[3];
    const float* w1    = (const float*)d_in[4];
    const float* b1    = (const float*)d_in[5];
    const float* w2    = (const float*)d_in[6];
    const float* b2    = (const float*)d_in[7];
    const float* emb10 = (const float*)d_in[8];
    const float* fc1w  = (const float*)d_in[9];
    const float* fc1b  = (const float*)d_in[10];
    const float* fc2w  = (const float*)d_in[11];
    const float* fc2b  = (const float*)d_in[12];
    const float* fc3w  = (const float*)d_in[13];
    const float* fc3b  = (const float*)d_in[14];
    float* out = (float*)d_out;

    prep<<<384, 256>>>(x, emb10);
    gc_gemm<<<NBLK, 256>>>(emb, w0, b0, w1, b1, w2, b2);
    mlp_kernel<<<NB, 512>>>(x, emb, emb10, fc1w, fc1b, fc2w, fc2b, fc3w, fc3b, out);
}

// round 11
// speedup vs baseline: 1.1651x; 1.1651x over previous
#include <cuda_runtime.h>
#include <math.h>

#define EDIM   128
#define LSEQ   512
#define NB     16
#define NFEAT  32
#define NBINS  8193
#define LAMBDA 0.01f

typedef unsigned long long u64;

// Persistent scratch. Index p is the PERMUTED bin order (DIF slot order):
// p = r*256 + m holds f = 32*rev9(2m) + r ; p = 8192 holds f = 8192.
// gc_gemm only sums over bins, so order is irrelevant as long as d_X and
// d_TA/d_TB agree (identical FFT structure on both paths).
__device__ __align__(256) float2 d_X[NB][8200];
__device__ __align__(256) float  d_H1[NB][EDIM * 8];
__device__ __align__(256) float  d_TA[8200][8];
__device__ __align__(256) float  d_TB[8200][8];

// ---- packed f32x2 helpers ----
__device__ __forceinline__ u64 fma2(u64 a, u64 b, u64 c) {
    u64 d; asm("fma.rn.f32x2 %0, %1, %2, %3;" : "=l"(d) : "l"(a), "l"(b), "l"(c));
    return d;
}
__device__ __forceinline__ u64 add2(u64 a, u64 b) {
    u64 d; asm("add.rn.f32x2 %0, %1, %2;" : "=l"(d) : "l"(a), "l"(b));
    return d;
}
__device__ __forceinline__ u64 pack2(float v) {
    u64 d; asm("mov.b64 %0, {%1, %1};" : "=l"(d) : "f"(v)); return d;
}
__device__ __forceinline__ u64 packpair(float a, float b) {
    u64 d; asm("mov.b64 %0, {%1, %2};" : "=l"(d) : "f"(a), "f"(b)); return d;
}
__device__ __forceinline__ float2 unpack2(u64 p) {
    float2 r; asm("mov.b64 {%0, %1}, %2;" : "=f"(r.x), "=f"(r.y) : "l"(p));
    return r;
}
__device__ __forceinline__ u64 relu2(u64 v) {
    float2 u = unpack2(v);
    return packpair(fmaxf(u.x, 0.0f), fmaxf(u.y, 0.0f));
}

__device__ __forceinline__ float2 cmul(float2 a, float2 b) {
    return make_float2(a.x * b.x - a.y * b.y, a.x * b.y + a.y * b.x);
}
__device__ __forceinline__ float2 cadd(float2 a, float2 b) {
    return make_float2(a.x + b.x, a.y + b.y);
}
__device__ __forceinline__ float2 csub(float2 a, float2 b) {
    return make_float2(a.x - b.x, a.y - b.y);
}

#define PAD(i) ((i) + ((i) >> 4))

// ---------------------------------------------------------------------------
// Kernel 1: PREP (R8 radix-4 DIF, proven). 384 blocks x 256 threads.
// ---------------------------------------------------------------------------
__global__ void __launch_bounds__(256)
prep(const float* __restrict__ x, const float* __restrict__ emb10) {
    __shared__ float2 buf[2][546];
    __shared__ float2 tw[256];
    __shared__ float2 w32[2][32];
    const int tid = threadIdx.x;
    const int sub = tid >> 7;
    const int t   = tid & 127;
    const int fftid = blockIdx.x * 2 + sub;
    const bool fwd = (fftid < 512);
    const int idx = fwd ? fftid : fftid - 512;
    const int r = idx & 31;
    float2* B = buf[sub];

    {
        float s, c;
        sincospif((float)tid * (1.0f / 256.0f), &s, &c);
        tw[tid] = make_float2(c, -s);
    }
    if (t < 32) {
        int ph = (r * t) & 31;
        float s, c;
        sincospif((float)ph * (1.0f / 16.0f), &s, &c);
        w32[sub][t] = make_float2(c, -s);
    }
    __syncthreads();

    if (fwd) {
        const int b = idx >> 5;
        #pragma unroll
        for (int li = 0; li < 4; li++) {
            const int l = t + 128 * li;
            const float4* xr4 = (const float4*)(x + (b * LSEQ + l) * NFEAT);
            float sr = 0.0f, si = 0.0f;
            #pragma unroll
            for (int i = 0; i < 8; i++) {
                float4 v4 = xr4[i];
                float2 wa = w32[sub][4 * i + 0], wb = w32[sub][4 * i + 1];
                float2 wc = w32[sub][4 * i + 2], wd = w32[sub][4 * i + 3];
                sr = fmaf(v4.x, wa.x, sr); si = fmaf(v4.x, wa.y, si);
                sr = fmaf(v4.y, wb.x, sr); si = fmaf(v4.y, wb.y, si);
                sr = fmaf(v4.z, wc.x, sr); si = fmaf(v4.z, wc.y, si);
                sr = fmaf(v4.w, wd.x, sr); si = fmaf(v4.w, wd.y, si);
            }
            float ss, cc;
            sincospif((float)(r * l) * (1.0f / 8192.0f), &ss, &cc);
            B[PAD(l)] = make_float2(fmaf(sr, cc, si * ss), fmaf(si, cc, -sr * ss));
        }
    } else {
        const int j = idx >> 5;
        #pragma unroll
        for (int li = 0; li < 4; li++) {
            const int l = t + 128 * li;
            float ev = emb10[l * 8 + j];
            float ss, cc;
            sincospif((float)(r * l) * (1.0f / 8192.0f), &ss, &cc);
            B[PAD(l)] = make_float2(ev * cc, -ev * ss);
        }
    }
    __syncthreads();

    #pragma unroll
    for (int s = 8; s >= 2; s -= 2) {
        const int h = 1 << s, h2 = h >> 1;
        const int j = t & (h2 - 1);
        const int base = ((t >> (s - 1)) << (s + 1)) + j;
        float2 a  = B[PAD(base)];
        float2 bb = B[PAD(base + h2)];
        float2 c  = B[PAD(base + h)];
        float2 d  = B[PAD(base + h + h2)];
        float2 wA = tw[j << (8 - s)];
        float2 wB = tw[(j + h2) << (8 - s)];
        float2 a1 = cadd(a, c),  c1 = cmul(csub(a, c),  wA);
        float2 b1 = cadd(bb, d), d1 = cmul(csub(bb, d), wB);
        float2 w2 = tw[j << (9 - s)];
        B[PAD(base)]          = cadd(a1, b1);
        B[PAD(base + h2)]     = cmul(csub(a1, b1), w2);
        B[PAD(base + h)]      = cadd(c1, d1);
        B[PAD(base + h + h2)] = cmul(csub(c1, d1), w2);
        __syncthreads();
    }
    #pragma unroll
    for (int k = 0; k < 2; k++) {
        int i = t + 128 * k;
        float2 u = B[PAD(2 * i)];
        float2 v = B[PAD(2 * i + 1)];
        B[PAD(2 * i)]     = cadd(u, v);
        B[PAD(2 * i + 1)] = csub(u, v);
    }
    __syncthreads();

    if (fwd) {
        const int b = idx >> 5;
        const float sc = 1.0f / 128.0f;
        #pragma unroll
        for (int k = 0; k < 2; k++) {
            int m = t + 128 * k;
            float2 v = B[PAD(2 * m)];
            d_X[b][r * 256 + m] = make_float2(v.x * sc, v.y * sc);
        }
        if (r == 0 && t == 0) {
            float2 v = B[PAD(1)];
            d_X[b][8192] = make_float2(v.x * sc, v.y * sc);
        }
    } else {
        const int j = idx >> 5;
        #pragma unroll
        for (int k = 0; k < 2; k++) {
            int m = t + 128 * k;
            int p = r * 256 + m;
            float sf = (p == 0) ? (1.0f / 128.0f) : (2.0f / 128.0f);
            float2 v = B[PAD(2 * m)];
            d_TA[p][j] = sf * v.x;
            d_TB[p][j] = sf * v.y;
        }
        if (r == 0 && t == 0) {
            float2 v = B[PAD(1)];
            d_TA[8192][j] = (1.0f / 128.0f) * v.x;
            d_TB[8192][j] = (1.0f / 128.0f) * v.y;
        }
    }
}

// ---------------------------------------------------------------------------
// Kernel 2: gc_gemm (R8 structure: block = 4e x 2b, threads over f) with
// explicit double-buffered prefetch of X and table rows.
// ---------------------------------------------------------------------------
__global__ void __launch_bounds__(256)
gc_gemm(const float* __restrict__ emb,
        const float* __restrict__ w0, const float* __restrict__ b0,
        const float* __restrict__ w1, const float* __restrict__ b1,
        const float* __restrict__ w2, const float* __restrict__ b2) {
    const int e0  = blockIdx.x * 4;
    const int b0i = blockIdx.y * 2;
    const int tid = threadIdx.x;

    u64 pD00[2], pD01[2], pD01n[2], pC00[2], pC01[2];
    u64 pd10[2], pd11[2], pd11n[2], pC10[2], pC11[2];
    u64 pd20[2], pd21[2], pd21n[2], pC20[2], pC21[2];
    #pragma unroll
    for (int pp = 0; pp < 2; pp++) {
        int eA = e0 + 2 * pp, eB = eA + 1;
        float emA = emb[eA], emB = emb[eB];
        float a01 = emA * w0[16384 + eA * 129], q01 = emB * w0[16384 + eB * 129];
        pD00[pp]  = packpair(emA * w0[eA * 129], emB * w0[eB * 129]);
        pD01[pp]  = packpair(a01, q01);
        pD01n[pp] = packpair(-a01, -q01);
        pC00[pp]  = packpair(b0[eA], b0[eB]);
        pC01[pp]  = packpair(b0[128 + eA], b0[128 + eB]);
        float a11 = w1[16384 + eA * 129], q11 = w1[16384 + eB * 129];
        pd10[pp]  = packpair(w1[eA * 129], w1[eB * 129]);
        pd11[pp]  = packpair(a11, q11);
        pd11n[pp] = packpair(-a11, -q11);
        pC10[pp]  = packpair(b1[eA], b1[eB]);
        pC11[pp]  = packpair(b1[128 + eA], b1[128 + eB]);
        float a21 = w2[16384 + eA * 129], q21 = w2[16384 + eB * 129];
        pd20[pp]  = packpair(w2[eA * 129], w2[eB * 129]);
        pd21[pp]  = packpair(a21, q21);
        pd21n[pp] = packpair(-a21, -q21);
        pC20[pp]  = packpair(b2[eA], b2[eB]);
        pC21[pp]  = packpair(b2[128 + eA], b2[128 + eB]);
    }
    const u64 NL = pack2(-LAMBDA);

    u64 acc[2][4][4];
    #pragma unroll
    for (int bb = 0; bb < 2; bb++)
        #pragma unroll
        for (int eo = 0; eo < 4; eo++)
            #pragma unroll
            for (int jp = 0; jp < 4; jp++) acc[bb][eo][jp] = 0ull;

    // ---- prefetch pipeline ----
    float2 nX0 = d_X[b0i][tid];
    float2 nX1 = d_X[b0i + 1][tid];
    ulonglong2 ntaL = *(const ulonglong2*)&d_TA[tid][0];
    ulonglong2 ntaH = *(const ulonglong2*)&d_TA[tid][4];
    ulonglong2 ntbL = *(const ulonglong2*)&d_TB[tid][0];
    ulonglong2 ntbH = *(const ulonglong2*)&d_TB[tid][4];

    for (int p = tid; p < NBINS; p += 256) {
        float2 X0 = nX0, X1 = nX1;
        ulonglong2 taL = ntaL, taH = ntaH, tbL = ntbL, tbH = ntbH;
        int pn = p + 256;
        if (pn < NBINS) {
            nX0  = d_X[b0i][pn];
            nX1  = d_X[b0i + 1][pn];
            ntaL = *(const ulonglong2*)&d_TA[pn][0];
            ntaH = *(const ulonglong2*)&d_TA[pn][4];
            ntbL = *(const ulonglong2*)&d_TB[pn][0];
            ntbH = *(const ulonglong2*)&d_TB[pn][4];
        }
        #pragma unroll
        for (int bb = 0; bb < 2; bb++) {
            u64 xr2 = pack2(bb ? X1.x : X0.x);
            u64 xi2 = pack2(bb ? X1.y : X0.y);
            #pragma unroll
            for (int pp = 0; pp < 2; pp++) {
                u64 r1r = fma2(xr2, pD00[pp], fma2(xi2, pD01n[pp], pC00[pp]));
                u64 o1r = relu2(r1r);
                u64 r1i = fma2(xi2, pD00[pp], fma2(xr2, pD01[pp], pC01[pp]));
                u64 o1i = relu2(r1i);
                u64 pr = relu2(add2(r1r, NL));
                u64 pi = relu2(add2(r1i, NL));
                u64 r2r = fma2(o1r, pd10[pp], fma2(o1i, pd11n[pp], pC10[pp]));
                u64 o2r = relu2(r2r);
                u64 r2i = fma2(o1i, pd10[pp], fma2(o2r, pd11[pp], pC11[pp]));
                u64 o2i = relu2(r2i);
                pr = add2(pr, relu2(add2(r2r, NL)));
                pi = add2(pi, relu2(add2(r2i, NL)));
                u64 r3r = fma2(o2r, pd20[pp], fma2(o2i, pd21n[pp], pC20[pp]));
                u64 o3r = relu2(r3r);
                u64 r3i = fma2(o2i, pd20[pp], fma2(o3r, pd21[pp], pC21[pp]));
                u64 zr2 = add2(pr, relu2(add2(r3r, NL)));
                u64 zi2 = add2(pi, relu2(add2(r3i, NL)));
                float2 zrv = unpack2(zr2), ziv = unpack2(zi2);
                {
                    u64 zr = pack2(zrv.x), zi = pack2(ziv.x);
                    u64* A = acc[bb][2 * pp];
                    A[0] = fma2(zr, taL.x, fma2(zi, tbL.x, A[0]));
                    A[1] = fma2(zr, taL.y, fma2(zi, tbL.y, A[1]));
                    A[2] = fma2(zr, taH.x, fma2(zi, tbH.x, A[2]));
                    A[3] = fma2(zr, taH.y, fma2(zi, tbH.y, A[3]));
                }
                {
                    u64 zr = pack2(zrv.y), zi = pack2(ziv.y);
                    u64* A = acc[bb][2 * pp + 1];
                    A[0] = fma2(zr, taL.x, fma2(zi, tbL.x, A[0]));
                    A[1] = fma2(zr, taL.y, fma2(zi, tbL.y, A[1]));
                    A[2] = fma2(zr, taH.x, fma2(zi, tbH.x, A[2]));
                    A[3] = fma2(zr, taH.y, fma2(zi, tbH.y, A[3]));
                }
            }
        }
    }

    __shared__ float red[8][64];
    const int lane = tid & 31, w = tid >> 5;
    #pragma unroll
    for (int bb = 0; bb < 2; bb++) {
        #pragma unroll
        for (int eo = 0; eo < 4; eo++) {
            #pragma unroll
            for (int jp = 0; jp < 4; jp++) {
                float2 pv = unpack2(acc[bb][eo][jp]);
                #pragma unroll
                for (int o = 16; o; o >>= 1) {
                    pv.x += __shfl_down_sync(0xFFFFFFFFu, pv.x, o);
                    pv.y += __shfl_down_sync(0xFFFFFFFFu, pv.y, o);
                }
                if (lane == 0) {
                    red[w][bb * 32 + eo * 8 + 2 * jp]     = pv.x;
                    red[w][bb * 32 + eo * 8 + 2 * jp + 1] = pv.y;
                }
            }
        }
        __syncwarp();
    }
    __syncthreads();
    if (tid < 64) {
        float s = 0.0f;
        #pragma unroll
        for (int ww = 0; ww < 8; ww++) s += red[ww][tid];
        d_H1[b0i + (tid >> 5)][e0 * 8 + (tid & 31)] = s;
    }
}

// ---------------------------------------------------------------------------
// Kernel 3: bias projection + final MLP (R8, proven). 16 blocks x 512 threads.
// ---------------------------------------------------------------------------
__global__ void __launch_bounds__(512)
mlp_kernel(const float* __restrict__ x, const float* __restrict__ emb,
           const float* __restrict__ emb10,
           const float* __restrict__ fc1w, const float* __restrict__ fc1b,
           const float* __restrict__ fc2w, const float* __restrict__ fc2b,
           const float* __restrict__ fc3w, const float* __restrict__ fc3b,
           float* __restrict__ out) {
    __shared__ __align__(16) float h[1024];
    __shared__ __align__(16) float v1[64];
    __shared__ __align__(16) float v2[256];
    __shared__ float xs[LSEQ];
    __shared__ float Ps[8];
    const int b = blockIdx.x;
    const int tid = threadIdx.x;
    const int w = tid >> 5, lane = tid & 31;

    xs[tid] = x[(b * LSEQ + tid) * NFEAT];
    __syncthreads();
    if (w < 8) {
        float s = 0.0f;
        #pragma unroll
        for (int i = 0; i < 16; i++)
            s += xs[lane + 32 * i] * emb10[(lane + 32 * i) * 8 + w];
        #pragma unroll
        for (int o = 16; o; o >>= 1) s += __shfl_down_sync(0xFFFFFFFFu, s, o);
        if (lane == 0) Ps[w] = s;
    }
    __syncthreads();

    #pragma unroll
    for (int k = 0; k < 2; k++) {
        int i = tid + 512 * k;
        h[i] = d_H1[b][i] + emb[i >> 3] * Ps[i & 7];
    }
    __syncthreads();

    {
        const int j = tid >> 3, sub = tid & 7;
        const float4* fw = (const float4*)(fc1w + j * 1024);
        const float4* h4 = (const float4*)h;
        float s = 0.0f;
        #pragma unroll
        for (int i = 0; i < 32; i++) {
            float4 a = fw[sub + 8 * i];
            float4 v = h4[sub + 8 * i];
            s += a.x * v.x + a.y * v.y + a.z * v.z + a.w * v.w;
        }
        s += __shfl_down_sync(0xFFFFFFFFu, s, 4, 8);
        s += __shfl_down_sync(0xFFFFFFFFu, s, 2, 8);
        s += __shfl_down_sync(0xFFFFFFFFu, s, 1, 8);
        if (sub == 0) {
            s += fc1b[j];
            v1[j] = s > 0.0f ? s : 0.01f * s;
        }
    }
    __syncthreads();

    {
        const int j = tid >> 1, sub = tid & 1;
        const float4* fw = (const float4*)(fc2w + j * 64);
        const float4* v14 = (const float4*)v1;
        float s = 0.0f;
        #pragma unroll
        for (int i = 0; i < 8; i++) {
            float4 a = fw[sub * 8 + i];
            float4 v = v14[sub * 8 + i];
            s += a.x * v.x + a.y * v.y + a.z * v.z + a.w * v.w;
        }
        s += __shfl_down_sync(0xFFFFFFFFu, s, 1, 2);
        if (sub == 0) {
            s += fc2b[j];
            v2[j] = s > 0.0f ? s : 0.01f * s;
        }
    }
    __syncthreads();

    if (tid < 384) {
        const int j = tid >> 2, sub = tid & 3;
        const float4* fw = (const float4*)(fc3w + j * 256);
        const float4* v24 = (const float4*)v2;
        float s = 0.0f;
        #pragma unroll
        for (int i = 0; i < 16; i++) {
            float4 a = fw[sub * 16 + i];
            float4 v = v24[sub * 16 + i];
            s += a.x * v.x + a.y * v.y + a.z * v.z + a.w * v.w;
        }
        s += __shfl_down_sync(0xFFFFFFFFu, s, 2, 4);
        s += __shfl_down_sync(0xFFFFFFFFu, s, 1, 4);
        if (sub == 0) out[b * 96 + j] = s + fc3b[j];
    }
}

// ---------------------------------------------------------------------------
extern "C" void kernel_launch(void* const* d_in, const int* in_sizes, int n_in,
                              void* d_out, int out_size) {
    const float* x     = (const float*)d_in[0];
    const float* emb   = (const float*)d_in[1];
    const float* w0    = (const float*)d_in[2];
    const float* b0    = (const float*)d_in[3];
    const float* w1    = (const float*)d_in[4];
    const float* b1    = (const float*)d_in[5];
    const float* w2    = (const float*)d_in[6];
    const float* b2    = (const float*)d_in[7];
    const float* emb10 = (const float*)d_in[8];
    const float* fc1w  = (const float*)d_in[9];
    const float* fc1b  = (const float*)d_in[10];
    const float* fc2w  = (const float*)d_in[11];
    const float* fc2b  = (const float*)d_in[12];
    const float* fc3w  = (const float*)d_in[13];
    const float* fc3b  = (const float*)d_in[14];
    float* out = (float*)d_out;

    prep<<<384, 256>>>(x, emb10);
    gc_gemm<<<dim3(32, 8), 256>>>(emb, w0, b0, w1, b1, w2, b2);
    mlp_kernel<<<NB, 512>>>(x, emb, emb10, fc1w, fc1b, fc2w, fc2b, fc3w, fc3b, out);
}

// round 12
// speedup vs baseline: 1.1666x; 1.0013x over previous
#include <cuda_runtime.h>
#include <cuda_fp16.h>
#include <math.h>

#define EDIM   128
#define LSEQ   512
#define NB     16
#define NFEAT  32
#define NBINS  8193
#define LAMBDA 0.01f

typedef unsigned long long u64;

// Persistent scratch. Index p is the PERMUTED bin order (DIF slot order):
// p = r*256 + m holds f = 32*rev9(2m) + r ; p = 8192 holds f = 8192.
// gc_gemm only sums over bins, so order is irrelevant as long as d_X and
// the table agree (identical FFT structure on both paths).
__device__ __align__(256) float2 d_X[NB][8200];
__device__ __align__(256) float  d_H1[NB][EDIM * 8];
// fp16 table: row p = [TA[0..7], TB[0..7]] (32 bytes)
__device__ __align__(256) __half d_Th[8200][16];

// ---- packed f32x2 helpers ----
__device__ __forceinline__ u64 fma2(u64 a, u64 b, u64 c) {
    u64 d; asm("fma.rn.f32x2 %0, %1, %2, %3;" : "=l"(d) : "l"(a), "l"(b), "l"(c));
    return d;
}
__device__ __forceinline__ u64 add2(u64 a, u64 b) {
    u64 d; asm("add.rn.f32x2 %0, %1, %2;" : "=l"(d) : "l"(a), "l"(b));
    return d;
}
__device__ __forceinline__ u64 pack2(float v) {
    u64 d; asm("mov.b64 %0, {%1, %1};" : "=l"(d) : "f"(v)); return d;
}
__device__ __forceinline__ u64 packpair(float a, float b) {
    u64 d; asm("mov.b64 %0, {%1, %2};" : "=l"(d) : "f"(a), "f"(b)); return d;
}
__device__ __forceinline__ float2 unpack2(u64 p) {
    float2 r; asm("mov.b64 {%0, %1}, %2;" : "=f"(r.x), "=f"(r.y) : "l"(p));
    return r;
}
__device__ __forceinline__ u64 relu2(u64 v) {
    float2 u = unpack2(v);
    return packpair(fmaxf(u.x, 0.0f), fmaxf(u.y, 0.0f));
}
// half2 word -> packed f32x2 (u64)
__device__ __forceinline__ u64 h2_to_pk(unsigned int w) {
    float2 f = __half22float2(*(const __half2*)&w);
    return packpair(f.x, f.y);
}

__device__ __forceinline__ float2 cmul(float2 a, float2 b) {
    return make_float2(a.x * b.x - a.y * b.y, a.x * b.y + a.y * b.x);
}
__device__ __forceinline__ float2 cadd(float2 a, float2 b) {
    return make_float2(a.x + b.x, a.y + b.y);
}
__device__ __forceinline__ float2 csub(float2 a, float2 b) {
    return make_float2(a.x - b.x, a.y - b.y);
}

#define PAD(i) ((i) + ((i) >> 4))

// ---------------------------------------------------------------------------
// Kernel 1: PREP (R8 radix-4 DIF, proven). 384 blocks x 256 threads.
// ---------------------------------------------------------------------------
__global__ void __launch_bounds__(256)
prep(const float* __restrict__ x, const float* __restrict__ emb10) {
    __shared__ float2 buf[2][546];
    __shared__ float2 tw[256];
    __shared__ float2 w32[2][32];
    const int tid = threadIdx.x;
    const int sub = tid >> 7;
    const int t   = tid & 127;
    const int fftid = blockIdx.x * 2 + sub;
    const bool fwd = (fftid < 512);
    const int idx = fwd ? fftid : fftid - 512;
    const int r = idx & 31;
    float2* B = buf[sub];

    {
        float s, c;
        sincospif((float)tid * (1.0f / 256.0f), &s, &c);
        tw[tid] = make_float2(c, -s);
    }
    if (t < 32) {
        int ph = (r * t) & 31;
        float s, c;
        sincospif((float)ph * (1.0f / 16.0f), &s, &c);
        w32[sub][t] = make_float2(c, -s);
    }
    __syncthreads();

    if (fwd) {
        const int b = idx >> 5;
        #pragma unroll
        for (int li = 0; li < 4; li++) {
            const int l = t + 128 * li;
            const float4* xr4 = (const float4*)(x + (b * LSEQ + l) * NFEAT);
            float sr = 0.0f, si = 0.0f;
            #pragma unroll
            for (int i = 0; i < 8; i++) {
                float4 v4 = xr4[i];
                float2 wa = w32[sub][4 * i + 0], wb = w32[sub][4 * i + 1];
                float2 wc = w32[sub][4 * i + 2], wd = w32[sub][4 * i + 3];
                sr = fmaf(v4.x, wa.x, sr); si = fmaf(v4.x, wa.y, si);
                sr = fmaf(v4.y, wb.x, sr); si = fmaf(v4.y, wb.y, si);
                sr = fmaf(v4.z, wc.x, sr); si = fmaf(v4.z, wc.y, si);
                sr = fmaf(v4.w, wd.x, sr); si = fmaf(v4.w, wd.y, si);
            }
            float ss, cc;
            sincospif((float)(r * l) * (1.0f / 8192.0f), &ss, &cc);
            B[PAD(l)] = make_float2(fmaf(sr, cc, si * ss), fmaf(si, cc, -sr * ss));
        }
    } else {
        const int j = idx >> 5;
        #pragma unroll
        for (int li = 0; li < 4; li++) {
            const int l = t + 128 * li;
            float ev = emb10[l * 8 + j];
            float ss, cc;
            sincospif((float)(r * l) * (1.0f / 8192.0f), &ss, &cc);
            B[PAD(l)] = make_float2(ev * cc, -ev * ss);
        }
    }
    __syncthreads();

    #pragma unroll
    for (int s = 8; s >= 2; s -= 2) {
        const int h = 1 << s, h2 = h >> 1;
        const int j = t & (h2 - 1);
        const int base = ((t >> (s - 1)) << (s + 1)) + j;
        float2 a  = B[PAD(base)];
        float2 bb = B[PAD(base + h2)];
        float2 c  = B[PAD(base + h)];
        float2 d  = B[PAD(base + h + h2)];
        float2 wA = tw[j << (8 - s)];
        float2 wB = tw[(j + h2) << (8 - s)];
        float2 a1 = cadd(a, c),  c1 = cmul(csub(a, c),  wA);
        float2 b1 = cadd(bb, d), d1 = cmul(csub(bb, d), wB);
        float2 w2 = tw[j << (9 - s)];
        B[PAD(base)]          = cadd(a1, b1);
        B[PAD(base + h2)]     = cmul(csub(a1, b1), w2);
        B[PAD(base + h)]      = cadd(c1, d1);
        B[PAD(base + h + h2)] = cmul(csub(c1, d1), w2);
        __syncthreads();
    }
    #pragma unroll
    for (int k = 0; k < 2; k++) {
        int i = t + 128 * k;
        float2 u = B[PAD(2 * i)];
        float2 v = B[PAD(2 * i + 1)];
        B[PAD(2 * i)]     = cadd(u, v);
        B[PAD(2 * i + 1)] = csub(u, v);
    }
    __syncthreads();

    if (fwd) {
        const int b = idx >> 5;
        const float sc = 1.0f / 128.0f;
        #pragma unroll
        for (int k = 0; k < 2; k++) {
            int m = t + 128 * k;
            float2 v = B[PAD(2 * m)];
            d_X[b][r * 256 + m] = make_float2(v.x * sc, v.y * sc);
        }
        if (r == 0 && t == 0) {
            float2 v = B[PAD(1)];
            d_X[b][8192] = make_float2(v.x * sc, v.y * sc);
        }
    } else {
        const int j = idx >> 5;
        #pragma unroll
        for (int k = 0; k < 2; k++) {
            int m = t + 128 * k;
            int p = r * 256 + m;
            float sf = (p == 0) ? (1.0f / 128.0f) : (2.0f / 128.0f);
            float2 v = B[PAD(2 * m)];
            d_Th[p][j]     = __float2half_rn(sf * v.x);
            d_Th[p][8 + j] = __float2half_rn(sf * v.y);
        }
        if (r == 0 && t == 0) {
            float2 v = B[PAD(1)];
            d_Th[8192][j]     = __float2half_rn((1.0f / 128.0f) * v.x);
            d_Th[8192][8 + j] = __float2half_rn((1.0f / 128.0f) * v.y);
        }
    }
}

// ---------------------------------------------------------------------------
// Kernel 2: gc_gemm (R8 structure: block = 4e x 2b, threads over f),
// fp16 table (32B/row instead of 64B).
// ---------------------------------------------------------------------------
__global__ void __launch_bounds__(256)
gc_gemm(const float* __restrict__ emb,
        const float* __restrict__ w0, const float* __restrict__ b0,
        const float* __restrict__ w1, const float* __restrict__ b1,
        const float* __restrict__ w2, const float* __restrict__ b2) {
    const int e0  = blockIdx.x * 4;
    const int b0i = blockIdx.y * 2;
    const int tid = threadIdx.x;

    u64 pD00[2], pD01[2], pD01n[2], pC00[2], pC01[2];
    u64 pd10[2], pd11[2], pd11n[2], pC10[2], pC11[2];
    u64 pd20[2], pd21[2], pd21n[2], pC20[2], pC21[2];
    #pragma unroll
    for (int pp = 0; pp < 2; pp++) {
        int eA = e0 + 2 * pp, eB = eA + 1;
        float emA = emb[eA], emB = emb[eB];
        float a01 = emA * w0[16384 + eA * 129], q01 = emB * w0[16384 + eB * 129];
        pD00[pp]  = packpair(emA * w0[eA * 129], emB * w0[eB * 129]);
        pD01[pp]  = packpair(a01, q01);
        pD01n[pp] = packpair(-a01, -q01);
        pC00[pp]  = packpair(b0[eA], b0[eB]);
        pC01[pp]  = packpair(b0[128 + eA], b0[128 + eB]);
        float a11 = w1[16384 + eA * 129], q11 = w1[16384 + eB * 129];
        pd10[pp]  = packpair(w1[eA * 129], w1[eB * 129]);
        pd11[pp]  = packpair(a11, q11);
        pd11n[pp] = packpair(-a11, -q11);
        pC10[pp]  = packpair(b1[eA], b1[eB]);
        pC11[pp]  = packpair(b1[128 + eA], b1[128 + eB]);
        float a21 = w2[16384 + eA * 129], q21 = w2[16384 + eB * 129];
        pd20[pp]  = packpair(w2[eA * 129], w2[eB * 129]);
        pd21[pp]  = packpair(a21, q21);
        pd21n[pp] = packpair(-a21, -q21);
        pC20[pp]  = packpair(b2[eA], b2[eB]);
        pC21[pp]  = packpair(b2[128 + eA], b2[128 + eB]);
    }
    const u64 NL = pack2(-LAMBDA);

    u64 acc[2][4][4];
    #pragma unroll
    for (int bb = 0; bb < 2; bb++)
        #pragma unroll
        for (int eo = 0; eo < 4; eo++)
            #pragma unroll
            for (int jp = 0; jp < 4; jp++) acc[bb][eo][jp] = 0ull;

    for (int p = tid; p < NBINS; p += 256) {
        float2 X0 = d_X[b0i][p];
        float2 X1 = d_X[b0i + 1][p];
        uint4 ha = *(const uint4*)&d_Th[p][0];    // TA halves 0..7
        uint4 hb = *(const uint4*)&d_Th[p][8];    // TB halves 0..7
        u64 taPk[4], tbPk[4];
        taPk[0] = h2_to_pk(ha.x); taPk[1] = h2_to_pk(ha.y);
        taPk[2] = h2_to_pk(ha.z); taPk[3] = h2_to_pk(ha.w);
        tbPk[0] = h2_to_pk(hb.x); tbPk[1] = h2_to_pk(hb.y);
        tbPk[2] = h2_to_pk(hb.z); tbPk[3] = h2_to_pk(hb.w);
        #pragma unroll
        for (int bb = 0; bb < 2; bb++) {
            u64 xr2 = pack2(bb ? X1.x : X0.x);
            u64 xi2 = pack2(bb ? X1.y : X0.y);
            #pragma unroll
            for (int pp = 0; pp < 2; pp++) {
                u64 r1r = fma2(xr2, pD00[pp], fma2(xi2, pD01n[pp], pC00[pp]));
                u64 o1r = relu2(r1r);
                u64 r1i = fma2(xi2, pD00[pp], fma2(xr2, pD01[pp], pC01[pp]));
                u64 o1i = relu2(r1i);
                u64 pr = relu2(add2(r1r, NL));
                u64 pi = relu2(add2(r1i, NL));
                u64 r2r = fma2(o1r, pd10[pp], fma2(o1i, pd11n[pp], pC10[pp]));
                u64 o2r = relu2(r2r);
                u64 r2i = fma2(o1i, pd10[pp], fma2(o2r, pd11[pp], pC11[pp]));
                u64 o2i = relu2(r2i);
                pr = add2(pr, relu2(add2(r2r, NL)));
                pi = add2(pi, relu2(add2(r2i, NL)));
                u64 r3r = fma2(o2r, pd20[pp], fma2(o2i, pd21n[pp], pC20[pp]));
                u64 o3r = relu2(r3r);
                u64 r3i = fma2(o2i, pd20[pp], fma2(o3r, pd21[pp], pC21[pp]));
                u64 zr2 = add2(pr, relu2(add2(r3r, NL)));
                u64 zi2 = add2(pi, relu2(add2(r3i, NL)));
                float2 zrv = unpack2(zr2), ziv = unpack2(zi2);
                {
                    u64 zr = pack2(zrv.x), zi = pack2(ziv.x);
                    u64* A = acc[bb][2 * pp];
                    A[0] = fma2(zr, taPk[0], fma2(zi, tbPk[0], A[0]));
                    A[1] = fma2(zr, taPk[1], fma2(zi, tbPk[1], A[1]));
                    A[2] = fma2(zr, taPk[2], fma2(zi, tbPk[2], A[2]));
                    A[3] = fma2(zr, taPk[3], fma2(zi, tbPk[3], A[3]));
                }
                {
                    u64 zr = pack2(zrv.y), zi = pack2(ziv.y);
                    u64* A = acc[bb][2 * pp + 1];
                    A[0] = fma2(zr, taPk[0], fma2(zi, tbPk[0], A[0]));
                    A[1] = fma2(zr, taPk[1], fma2(zi, tbPk[1], A[1]));
                    A[2] = fma2(zr, taPk[2], fma2(zi, tbPk[2], A[2]));
                    A[3] = fma2(zr, taPk[3], fma2(zi, tbPk[3], A[3]));
                }
            }
        }
    }

    __shared__ float red[8][64];
    const int lane = tid & 31, w = tid >> 5;
    #pragma unroll
    for (int bb = 0; bb < 2; bb++) {
        #pragma unroll
        for (int eo = 0; eo < 4; eo++) {
            #pragma unroll
            for (int jp = 0; jp < 4; jp++) {
                float2 pv = unpack2(acc[bb][eo][jp]);
                #pragma unroll
                for (int o = 16; o; o >>= 1) {
                    pv.x += __shfl_down_sync(0xFFFFFFFFu, pv.x, o);
                    pv.y += __shfl_down_sync(0xFFFFFFFFu, pv.y, o);
                }
                if (lane == 0) {
                    red[w][bb * 32 + eo * 8 + 2 * jp]     = pv.x;
                    red[w][bb * 32 + eo * 8 + 2 * jp + 1] = pv.y;
                }
            }
        }
        __syncwarp();
    }
    __syncthreads();
    if (tid < 64) {
        float s = 0.0f;
        #pragma unroll
        for (int ww = 0; ww < 8; ww++) s += red[ww][tid];
        d_H1[b0i + (tid >> 5)][e0 * 8 + (tid & 31)] = s;
    }
}

// ---------------------------------------------------------------------------
// Kernel 3: bias projection + final MLP (R8, proven). 16 blocks x 512 threads.
// ---------------------------------------------------------------------------
__global__ void __launch_bounds__(512)
mlp_kernel(const float* __restrict__ x, const float* __restrict__ emb,
           const float* __restrict__ emb10,
           const float* __restrict__ fc1w, const float* __restrict__ fc1b,
           const float* __restrict__ fc2w, const float* __restrict__ fc2b,
           const float* __restrict__ fc3w, const float* __restrict__ fc3b,
           float* __restrict__ out) {
    __shared__ __align__(16) float h[1024];
    __shared__ __align__(16) float v1[64];
    __shared__ __align__(16) float v2[256];
    __shared__ float xs[LSEQ];
    __shared__ float Ps[8];
    const int b = blockIdx.x;
    const int tid = threadIdx.x;
    const int w = tid >> 5, lane = tid & 31;

    xs[tid] = x[(b * LSEQ + tid) * NFEAT];
    __syncthreads();
    if (w < 8) {
        float s = 0.0f;
        #pragma unroll
        for (int i = 0; i < 16; i++)
            s += xs[lane + 32 * i] * emb10[(lane + 32 * i) * 8 + w];
        #pragma unroll
        for (int o = 16; o; o >>= 1) s += __shfl_down_sync(0xFFFFFFFFu, s, o);
        if (lane == 0) Ps[w] = s;
    }
    __syncthreads();

    #pragma unroll
    for (int k = 0; k < 2; k++) {
        int i = tid + 512 * k;
        h[i] = d_H1[b][i] + emb[i >> 3] * Ps[i & 7];
    }
    __syncthreads();

    {
        const int j = tid >> 3, sub = tid & 7;
        const float4* fw = (const float4*)(fc1w + j * 1024);
        const float4* h4 = (const float4*)h;
        float s = 0.0f;
        #pragma unroll
        for (int i = 0; i < 32; i++) {
            float4 a = fw[sub + 8 * i];
            float4 v = h4[sub + 8 * i];
            s += a.x * v.x + a.y * v.y + a.z * v.z + a.w * v.w;
        }
        s += __shfl_down_sync(0xFFFFFFFFu, s, 4, 8);
        s += __shfl_down_sync(0xFFFFFFFFu, s, 2, 8);
        s += __shfl_down_sync(0xFFFFFFFFu, s, 1, 8);
        if (sub == 0) {
            s += fc1b[j];
            v1[j] = s > 0.0f ? s : 0.01f * s;
        }
    }
    __syncthreads();

    {
        const int j = tid >> 1, sub = tid & 1;
        const float4* fw = (const float4*)(fc2w + j * 64);
        const float4* v14 = (const float4*)v1;
        float s = 0.0f;
        #pragma unroll
        for (int i = 0; i < 8; i++) {
            float4 a = fw[sub * 8 + i];
            float4 v = v14[sub * 8 + i];
            s += a.x * v.x + a.y * v.y + a.z * v.z + a.w * v.w;
        }
        s += __shfl_down_sync(0xFFFFFFFFu, s, 1, 2);
        if (sub == 0) {
            s += fc2b[j];
            v2[j] = s > 0.0f ? s : 0.01f * s;
        }
    }
    __syncthreads();

    if (tid < 384) {
        const int j = tid >> 2, sub = tid & 3;
        const float4* fw = (const float4*)(fc3w + j * 256);
        const float4* v24 = (const float4*)v2;
        float s = 0.0f;
        #pragma unroll
        for (int i = 0; i < 16; i++) {
            float4 a = fw[sub * 16 + i];
            float4 v = v24[sub * 16 + i];
            s += a.x * v.x + a.y * v.y + a.z * v.z + a.w * v.w;
        }
        s += __shfl_down_sync(0xFFFFFFFFu, s, 2, 4);
        s += __shfl_down_sync(0xFFFFFFFFu, s, 1, 4);
        if (sub == 0) out[b * 96 + j] = s + fc3b[j];
    }
}

// ---------------------------------------------------------------------------
extern "C" void kernel_launch(void* const* d_in, const int* in_sizes, int n_in,
                              void* d_out, int out_size) {
    const float* x     = (const float*)d_in[0];
    const float* emb   = (const float*)d_in[1];
    const float* w0    = (const float*)d_in[2];
    const float* b0    = (const float*)d_in[3];
    const float* w1    = (const float*)d_in[4];
    const float* b1    = (const float*)d_in[5];
    const float* w2    = (const float*)d_in[6];
    const float* b2    = (const float*)d_in[7];
    const float* emb10 = (const float*)d_in[8];
    const float* fc1w  = (const float*)d_in[9];
    const float* fc1b  = (const float*)d_in[10];
    const float* fc2w  = (const float*)d_in[11];
    const float* fc2b  = (const float*)d_in[12];
    const float* fc3w  = (const float*)d_in[13];
    const float* fc3b  = (const float*)d_in[14];
    float* out = (float*)d_out;

    prep<<<384, 256>>>(x, emb10);
    gc_gemm<<<dim3(32, 8), 256>>>(emb, w0, b0, w1, b1, w2, b2);
    mlp_kernel<<<NB, 512>>>(x, emb, emb10, fc1w, fc1b, fc2w, fc2b, fc3w, fc3b, out);
}